// round 10
// baseline (speedup 1.0000x reference)
#include <cuda_runtime.h>
#include <cuda_bf16.h>
#include <cstdint>
#include <cstddef>

#define B_  8
#define S_  1024
#define D_  1024
#define H_  16
#define DK_ 64
#define M_  (B_*S_)   // 8192
#define MD_ ((size_t)M_*D_)
#define DD_ ((size_t)D_*D_)

// ---------------------------------------------------------------------------
// Scratch (__device__ globals; allocation-free rule)
// ---------------------------------------------------------------------------
__device__ __nv_bfloat16 g_Xhi[3*MD_];  // split inputs q,k,v
__device__ __nv_bfloat16 g_Xlo[3*MD_];
__device__ __nv_bfloat16 g_Whi[4*DD_];  // split weights wq,wk,wv,wo
__device__ __nv_bfloat16 g_Wlo[4*DD_];
__device__ __nv_bfloat16 g_Ohi[MD_];    // split attention output [M,D]
__device__ __nv_bfloat16 g_Olo[MD_];

// head-major [B,H,S,DK] split Q/K/V
__device__ __nv_bfloat16 g_Qhi[MD_];
__device__ __nv_bfloat16 g_Qlo[MD_];
__device__ __nv_bfloat16 g_Khi[MD_];
__device__ __nv_bfloat16 g_Klo[MD_];
__device__ __nv_bfloat16 g_Vhi[MD_];
__device__ __nv_bfloat16 g_Vlo[MD_];

// ---------------------------------------------------------------------------
// PTX helpers — base ISA only: ldmatrix, mma.sync, cp.async
// ---------------------------------------------------------------------------
__device__ __forceinline__ uint32_t s2u(const void* p) {
    uint32_t a;
    asm("{ .reg .u64 t; cvta.to.shared.u64 t, %1; cvt.u32.u64 %0, t; }"
        : "=r"(a) : "l"(p));
    return a;
}

#define LDSM_X4(r0, r1, r2, r3, addr) \
    asm volatile("ldmatrix.sync.aligned.m8n8.x4.shared.b16 {%0,%1,%2,%3}, [%4];" \
        : "=r"(r0), "=r"(r1), "=r"(r2), "=r"(r3) : "r"(addr))

#define LDSM_X4T(r0, r1, r2, r3, addr) \
    asm volatile("ldmatrix.sync.aligned.m8n8.x4.trans.shared.b16 {%0,%1,%2,%3}, [%4];" \
        : "=r"(r0), "=r"(r1), "=r"(r2), "=r"(r3) : "r"(addr))

#define MMA16816(d, a, b0, b1) \
    asm volatile("mma.sync.aligned.m16n8k16.row.col.f32.bf16.bf16.f32 " \
        "{%0,%1,%2,%3}, {%4,%5,%6,%7}, {%8,%9}, {%0,%1,%2,%3};" \
        : "+f"((d)[0]), "+f"((d)[1]), "+f"((d)[2]), "+f"((d)[3]) \
        : "r"((a)[0]), "r"((a)[1]), "r"((a)[2]), "r"((a)[3]), "r"(b0), "r"(b1))

__device__ __forceinline__ void cpasync16(uint32_t dst, const void* src) {
    asm volatile("cp.async.cg.shared.global [%0], [%1], 16;" :: "r"(dst), "l"(src));
}
#define CP_COMMIT()  asm volatile("cp.async.commit_group;" ::: "memory")
#define CP_WAIT1()   asm volatile("cp.async.wait_group 1;" ::: "memory")
#define CP_WAIT0()   asm volatile("cp.async.wait_group 0;" ::: "memory")

// fp32 pair -> packed bf16x2 hi + lo (residual)
__device__ __forceinline__ void split2(float x, float y, uint32_t& hi, uint32_t& lo) {
    __nv_bfloat16 hx = __float2bfloat16(x), hy = __float2bfloat16(y);
    __nv_bfloat162 h2(hx, hy);
    hi = *reinterpret_cast<uint32_t*>(&h2);
    __nv_bfloat162 l2(__float2bfloat16(x - __bfloat162float(hx)),
                      __float2bfloat16(y - __bfloat162float(hy)));
    lo = *reinterpret_cast<uint32_t*>(&l2);
}

// ---------------------------------------------------------------------------
// Split converters (fp32 -> hi/lo bf16), batched over inputs / weights.
// ---------------------------------------------------------------------------
__global__ __launch_bounds__(256) void split_x3(
    const float* __restrict__ q, const float* __restrict__ k,
    const float* __restrict__ v)
{
    const int z = blockIdx.y;
    const float* __restrict__ s = (z == 0) ? q : (z == 1) ? k : v;
    const size_t base = (size_t)z * MD_;
    const int i = blockIdx.x * 256 + threadIdx.x;         // < M*D/4
    float4 vv = ((const float4*)s)[i];
    uint32_t h0, l0, h1, l1;
    split2(vv.x, vv.y, h0, l0);
    split2(vv.z, vv.w, h1, l1);
    uint32_t* hp = (uint32_t*)(g_Xhi + base);
    uint32_t* lp = (uint32_t*)(g_Xlo + base);
    hp[2 * i] = h0; hp[2 * i + 1] = h1;
    lp[2 * i] = l0; lp[2 * i + 1] = l1;
}

__global__ __launch_bounds__(256) void split_w4(
    const float* __restrict__ wq, const float* __restrict__ wk,
    const float* __restrict__ wv, const float* __restrict__ wo)
{
    const int z = blockIdx.y;
    const float* __restrict__ s = (z == 0) ? wq : (z == 1) ? wk : (z == 2) ? wv : wo;
    const size_t base = (size_t)z * DD_;
    const int i = blockIdx.x * 256 + threadIdx.x;         // < D*D/4
    float4 vv = ((const float4*)s)[i];
    uint32_t h0, l0, h1, l1;
    split2(vv.x, vv.y, h0, l0);
    split2(vv.z, vv.w, h1, l1);
    uint32_t* hp = (uint32_t*)(g_Whi + base);
    uint32_t* lp = (uint32_t*)(g_Wlo + base);
    hp[2 * i] = h0; hp[2 * i + 1] = h1;
    lp[2 * i] = l0; lp[2 * i + 1] = l1;
}

// ---------------------------------------------------------------------------
// HMMA split-bf16 GEMM: C[m,n] = sum_k X[m,k]*W[n,k] + bias[n]
// Block 128x128, 8 warps (4m x 2n), k-chunk 16, 3-stage cp.async, 48 KB smem.
// __launch_bounds__(256, 2): 2 CTAs/SM (regs capped at 128, smem 96 KB/SM).
// MODE 1: batched QKV (blockIdx.z selects input/weight/bias/dest, split write).
// MODE 0: output GEMM (X = g_Ohi/Olo, W slot 3, fp32 write to Y).
// ---------------------------------------------------------------------------
#define MAT_BYTES 4096       // 128 rows * 32 B
#define NCHUNK    (D_ / 16)  // 64

template <int MODE>
__global__ __launch_bounds__(256, 2) void gemm_mma(
    const float* __restrict__ b0p, const float* __restrict__ b1p,
    const float* __restrict__ b2p, float* __restrict__ Y)
{
    __shared__ __nv_bfloat16 smem[3 * 4 * 128 * 16];   // 48 KB
    const uint32_t sb = s2u(smem);

    const int z = (MODE == 1) ? blockIdx.z : 3;
    const __nv_bfloat16* __restrict__ Xhi = (MODE == 1) ? g_Xhi + (size_t)z * MD_ : g_Ohi;
    const __nv_bfloat16* __restrict__ Xlo = (MODE == 1) ? g_Xlo + (size_t)z * MD_ : g_Olo;
    const __nv_bfloat16* __restrict__ Whi = g_Whi + (size_t)z * DD_;
    const __nv_bfloat16* __restrict__ Wlo = g_Wlo + (size_t)z * DD_;
    const float* __restrict__ bias =
        (MODE == 1) ? ((z == 0) ? b0p : (z == 1) ? b1p : b2p) : b0p;

    const int tid  = threadIdx.x;
    const int wid  = tid >> 5, lane = tid & 31;
    const int wm0  = (wid & 3) * 32;
    const int wn0  = (wid >> 2) * 64;
    const int m0   = blockIdx.y * 128, n0 = blockIdx.x * 128;

    auto sm_off = [](int row, int ck) -> uint32_t {
        return (uint32_t)(row * 32 + ((ck ^ ((row >> 2) & 1)) << 4));
    };

    auto load_stage = [&](int c, int stage) {
        const int k0 = c * 16;
#pragma unroll
        for (int i = 0; i < 4; ++i) {
            const int qq  = tid + i * 256;
            const int mat = qq >> 8, idx = qq & 255;
            const int row = idx >> 1, ck = idx & 1;
            uint32_t dst = sb + (uint32_t)(stage * 4 + mat) * MAT_BYTES + sm_off(row, ck);
            const __nv_bfloat16* g =
                (mat == 0) ? Xhi : (mat == 1) ? Xlo : (mat == 2) ? Whi : Wlo;
            const int grow = (mat < 2) ? (m0 + row) : (n0 + row);
            cpasync16(dst, g + (size_t)grow * D_ + k0 + ck * 8);
        }
        CP_COMMIT();
    };

    float acc[2][8][4];
#pragma unroll
    for (int mt = 0; mt < 2; ++mt)
#pragma unroll
        for (int nt = 0; nt < 8; ++nt)
#pragma unroll
            for (int r = 0; r < 4; ++r) acc[mt][nt][r] = 0.f;

    load_stage(0, 0);
    load_stage(1, 1);

    for (int c = 0; c < NCHUNK; ++c) {
        if (c == NCHUNK - 1) { CP_WAIT0(); } else { CP_WAIT1(); }
        __syncthreads();
        if (c + 2 < NCHUNK) load_stage(c + 2, (c + 2) % 3);

        const int stage = c % 3;
        const uint32_t ahB = sb + (uint32_t)(stage * 4 + 0) * MAT_BYTES;
        const uint32_t alB = sb + (uint32_t)(stage * 4 + 1) * MAT_BYTES;
        const uint32_t bhB = sb + (uint32_t)(stage * 4 + 2) * MAT_BYTES;
        const uint32_t blB = sb + (uint32_t)(stage * 4 + 3) * MAT_BYTES;

        const int lrow = lane & 15, lck = lane >> 4;

        uint32_t ah[2][4], al[2][4], bb[4][4];
#pragma unroll
        for (int mt = 0; mt < 2; ++mt) {
            LDSM_X4(ah[mt][0], ah[mt][1], ah[mt][2], ah[mt][3],
                    ahB + sm_off(wm0 + mt * 16 + lrow, lck));
            LDSM_X4(al[mt][0], al[mt][1], al[mt][2], al[mt][3],
                    alB + sm_off(wm0 + mt * 16 + lrow, lck));
        }
#pragma unroll
        for (int bt = 0; bt < 4; ++bt)
            LDSM_X4(bb[bt][0], bb[bt][1], bb[bt][2], bb[bt][3],
                    bhB + sm_off(wn0 + bt * 16 + lrow, lck));

#pragma unroll
        for (int mt = 0; mt < 2; ++mt)
#pragma unroll
            for (int bt = 0; bt < 4; ++bt) {
                MMA16816(acc[mt][bt * 2 + 0], ah[mt], bb[bt][0], bb[bt][2]);
                MMA16816(acc[mt][bt * 2 + 1], ah[mt], bb[bt][1], bb[bt][3]);
                MMA16816(acc[mt][bt * 2 + 0], al[mt], bb[bt][0], bb[bt][2]);
                MMA16816(acc[mt][bt * 2 + 1], al[mt], bb[bt][1], bb[bt][3]);
            }

#pragma unroll
        for (int bt = 0; bt < 4; ++bt)
            LDSM_X4(bb[bt][0], bb[bt][1], bb[bt][2], bb[bt][3],
                    blB + sm_off(wn0 + bt * 16 + lrow, lck));
#pragma unroll
        for (int mt = 0; mt < 2; ++mt)
#pragma unroll
            for (int bt = 0; bt < 4; ++bt) {
                MMA16816(acc[mt][bt * 2 + 0], ah[mt], bb[bt][0], bb[bt][2]);
                MMA16816(acc[mt][bt * 2 + 1], ah[mt], bb[bt][1], bb[bt][3]);
            }

        __syncthreads();
    }

    const int trow = lane >> 2, tcol = (lane & 3) * 2;
#pragma unroll
    for (int mt = 0; mt < 2; ++mt) {
#pragma unroll
        for (int nt = 0; nt < 8; ++nt) {
            const int col = n0 + wn0 + (nt >> 1) * 16 + (nt & 1) * 8 + tcol;
            const float2 bv = *(const float2*)&bias[col];
#pragma unroll
            for (int rh = 0; rh < 2; ++rh) {
                const int row = m0 + wm0 + mt * 16 + trow + rh * 8;
                float2 o = make_float2(acc[mt][nt][rh * 2 + 0] + bv.x,
                                       acc[mt][nt][rh * 2 + 1] + bv.y);
                if (MODE == 0) {
                    *(float2*)&Y[(size_t)row * D_ + col] = o;
                } else {
                    const int b = row >> 10, s = row & 1023;
                    const int h = col >> 6, dk = col & 63;
                    const size_t idx = (((size_t)(b * H_ + h) * S_ + s) << 6) + dk;
                    uint32_t hi, lo;
                    split2(o.x, o.y, hi, lo);
                    __nv_bfloat16* dh = (z == 0) ? g_Qhi : (z == 1) ? g_Khi : g_Vhi;
                    __nv_bfloat16* dl = (z == 0) ? g_Qlo : (z == 1) ? g_Klo : g_Vlo;
                    *(uint32_t*)&dh[idx] = hi;
                    *(uint32_t*)&dl[idx] = lo;
                }
            }
        }
    }
}

// ---------------------------------------------------------------------------
// Flash attention via split-bf16 mma.sync.
// Block = (128 q-rows, h, b); 8 warps x 16 q-rows; k-tile = 64 keys.
// __launch_bounds__(256, 2): 2 CTAs/SM (regs capped at 128, smem 64 KB/SM) —
// doubles warps/SMSP to fix the occ=12.4%/issue=28% latency bound.
// K and V staged in separate cp.async groups: V load hidden behind S/softmax.
// Softmax in exp2 domain with folded 0.125*log2(e) scale.
// ---------------------------------------------------------------------------
#define SMOFF(r, c) ((uint32_t)((r) * 128 + ((((c) ^ ((r) & 7))) << 4)))
#define SCL2E 0.1803368801111204f   // 0.125 * log2(e)

__global__ __launch_bounds__(256, 2) void flash_mma(const int* __restrict__ mask)
{
    __shared__ __nv_bfloat16 smem[16384];   // 32 KB
    const uint32_t sb = s2u(smem);

    const int tid = threadIdx.x, wid = tid >> 5, lane = tid & 31;
    const int h = blockIdx.y, b = blockIdx.z;
    const int q0 = blockIdx.x * 128;
    const size_t bh = (size_t)(b * H_ + h) * S_;

    // ---- prologue: stage Q hi/lo, ldmatrix into registers ----
#pragma unroll
    for (int i = 0; i < 8; ++i) {
        int t = tid + i * 256;                       // 0..2047
        int mat = t >> 10, r = (t >> 3) & 127, ck = t & 7;
        const __nv_bfloat16* g = mat ? g_Qlo : g_Qhi;
        cpasync16(sb + (uint32_t)mat * 16384u + SMOFF(r, ck),
                  g + ((bh + q0 + r) << 6) + ck * 8);
    }
    CP_COMMIT(); CP_WAIT0();
    __syncthreads();

    const int lr = lane & 15, lc = lane >> 4;
    uint32_t qh[4][4], ql[4][4];
#pragma unroll
    for (int t = 0; t < 4; ++t) {
        LDSM_X4(qh[t][0], qh[t][1], qh[t][2], qh[t][3],
                sb + SMOFF(wid * 16 + lr, 2 * t + lc));
        LDSM_X4(ql[t][0], ql[t][1], ql[t][2], ql[t][3],
                sb + 16384u + SMOFF(wid * 16 + lr, 2 * t + lc));
    }

    float of[8][4];
    float mrow[2] = {-1e30f, -1e30f}, lrow[2] = {0.f, 0.f};
#pragma unroll
    for (int j = 0; j < 8; ++j)
#pragma unroll
        for (int r = 0; r < 4; ++r) of[j][r] = 0.f;

    const int trow = lane >> 2, tcol2 = (lane & 3) * 2;
    const int qrow0 = q0 + wid * 16 + trow;
    const int* mrow0 = mask + ((size_t)b * S_ + qrow0) * S_;
    const int* mrow1 = mrow0 + 8 * S_;

    for (int kt = 0; kt < 16; ++kt) {
        __syncthreads();                       // prior tile fully consumed
        const int k0g = kt * 64;
        // K group (Kh@0, Kl@8K)
#pragma unroll
        for (int i = 0; i < 4; ++i) {
            int t = tid + i * 256;             // 0..1023
            int mat = t >> 9, r = (t >> 3) & 63, ck = t & 7;
            const __nv_bfloat16* g = (mat == 0) ? g_Khi : g_Klo;
            cpasync16(sb + (uint32_t)mat * 8192u + SMOFF(r, ck),
                      g + ((bh + k0g + r) << 6) + ck * 8);
        }
        CP_COMMIT();
        // V group (Vh@16K, Vl@24K)
#pragma unroll
        for (int i = 4; i < 8; ++i) {
            int t = tid + i * 256;             // 1024..2047
            int mat = t >> 9, r = (t >> 3) & 63, ck = t & 7;
            const __nv_bfloat16* g = (mat == 2) ? g_Vhi : g_Vlo;
            cpasync16(sb + (uint32_t)mat * 8192u + SMOFF(r, ck),
                      g + ((bh + k0g + r) << 6) + ck * 8);
        }
        CP_COMMIT();

        CP_WAIT1();                            // K ready (V still in flight)
        __syncthreads();

        // ---- S = Q K^T (hh + hl + lh) ----
        float sf[8][4];
#pragma unroll
        for (int j = 0; j < 8; ++j)
#pragma unroll
            for (int r = 0; r < 4; ++r) sf[j][r] = 0.f;

#pragma unroll
        for (int t = 0; t < 4; ++t) {
#pragma unroll
            for (int nb = 0; nb < 4; ++nb) {
                uint32_t k0r, k1r, k2r, k3r, l0r, l1r, l2r, l3r;
                LDSM_X4(k0r, k1r, k2r, k3r, sb + SMOFF(nb * 16 + lr, 2 * t + lc));
                LDSM_X4(l0r, l1r, l2r, l3r, sb + 8192u + SMOFF(nb * 16 + lr, 2 * t + lc));
                MMA16816(sf[2 * nb + 0], qh[t], k0r, k2r);
                MMA16816(sf[2 * nb + 1], qh[t], k1r, k3r);
                MMA16816(sf[2 * nb + 0], qh[t], l0r, l2r);
                MMA16816(sf[2 * nb + 1], qh[t], l1r, l3r);
                MMA16816(sf[2 * nb + 0], ql[t], k0r, k2r);
                MMA16816(sf[2 * nb + 1], ql[t], k1r, k3r);
            }
        }

        // ---- scale (exp2 domain) + mask ----
#pragma unroll
        for (int j = 0; j < 8; ++j) {
            const int col = k0g + j * 8 + tcol2;
            int2 m0v = *(const int2*)&mrow0[col];
            int2 m1v = *(const int2*)&mrow1[col];
            sf[j][0] = m0v.x ? sf[j][0] * SCL2E : -1e30f;
            sf[j][1] = m0v.y ? sf[j][1] * SCL2E : -1e30f;
            sf[j][2] = m1v.x ? sf[j][2] * SCL2E : -1e30f;
            sf[j][3] = m1v.y ? sf[j][3] * SCL2E : -1e30f;
        }

        // ---- online softmax (exp2 domain; quad = lanes l^1, l^2) ----
#pragma unroll
        for (int hh = 0; hh < 2; ++hh) {
            float rm = -1e30f;
#pragma unroll
            for (int j = 0; j < 8; ++j)
                rm = fmaxf(rm, fmaxf(sf[j][2 * hh], sf[j][2 * hh + 1]));
            rm = fmaxf(rm, __shfl_xor_sync(0xffffffffu, rm, 1));
            rm = fmaxf(rm, __shfl_xor_sync(0xffffffffu, rm, 2));
            float mnew  = fmaxf(mrow[hh], rm);
            float alpha = exp2f(mrow[hh] - mnew);
            mrow[hh] = mnew;
            float ps = 0.f;
#pragma unroll
            for (int j = 0; j < 8; ++j) {
                sf[j][2 * hh]     = exp2f(sf[j][2 * hh] - mnew);
                sf[j][2 * hh + 1] = exp2f(sf[j][2 * hh + 1] - mnew);
                ps += sf[j][2 * hh] + sf[j][2 * hh + 1];
            }
            ps += __shfl_xor_sync(0xffffffffu, ps, 1);
            ps += __shfl_xor_sync(0xffffffffu, ps, 2);
            lrow[hh] = lrow[hh] * alpha + ps;
#pragma unroll
            for (int j = 0; j < 8; ++j) {
                of[j][2 * hh]     *= alpha;
                of[j][2 * hh + 1] *= alpha;
            }
        }

        CP_WAIT0();                            // V ready
        __syncthreads();

        // ---- O += P V (P split in registers; V via ldmatrix.trans) ----
#pragma unroll
        for (int t = 0; t < 4; ++t) {
            uint32_t pah[4], pal[4];
            split2(sf[2 * t][0],     sf[2 * t][1],     pah[0], pal[0]);
            split2(sf[2 * t][2],     sf[2 * t][3],     pah[1], pal[1]);
            split2(sf[2 * t + 1][0], sf[2 * t + 1][1], pah[2], pal[2]);
            split2(sf[2 * t + 1][2], sf[2 * t + 1][3], pah[3], pal[3]);
#pragma unroll
            for (int nb = 0; nb < 4; ++nb) {
                uint32_t v0, v1, v2, v3, w0, w1, w2, w3;
                LDSM_X4T(v0, v1, v2, v3, sb + 16384u + SMOFF(t * 16 + lr, 2 * nb + lc));
                LDSM_X4T(w0, w1, w2, w3, sb + 24576u + SMOFF(t * 16 + lr, 2 * nb + lc));
                MMA16816(of[2 * nb + 0], pah, v0, v1);
                MMA16816(of[2 * nb + 1], pah, v2, v3);
                MMA16816(of[2 * nb + 0], pah, w0, w1);
                MMA16816(of[2 * nb + 1], pah, w2, w3);
                MMA16816(of[2 * nb + 0], pal, v0, v1);
                MMA16816(of[2 * nb + 1], pal, v2, v3);
            }
        }
    }

    // ---- epilogue: normalize, split, write hi/lo bf16 [M,D] ----
#pragma unroll
    for (int hh = 0; hh < 2; ++hh) {
        const float inv = (lrow[hh] > 0.f) ? (1.f / lrow[hh]) : 0.f;
        const int row = qrow0 + 8 * hh;
        const size_t rb = ((size_t)b * S_ + row) * D_ + h * 64;
#pragma unroll
        for (int j = 0; j < 8; ++j) {
            uint32_t hi, lo;
            split2(of[j][2 * hh] * inv, of[j][2 * hh + 1] * inv, hi, lo);
            *(uint32_t*)&g_Ohi[rb + j * 8 + tcol2] = hi;
            *(uint32_t*)&g_Olo[rb + j * 8 + tcol2] = lo;
        }
    }
}

// ---------------------------------------------------------------------------
// kernel_launch: pure kernel launches, nothing else.
// ---------------------------------------------------------------------------
extern "C" void kernel_launch(void* const* d_in, const int* in_sizes, int n_in,
                              void* d_out, int out_size)
{
    const float* q    = (const float*)d_in[0];
    const float* k    = (const float*)d_in[1];
    const float* v    = (const float*)d_in[2];
    const int*   mask = (const int*)d_in[3];
    const float* wq   = (const float*)d_in[4];
    const float* bq   = (const float*)d_in[5];
    const float* wk   = (const float*)d_in[6];
    const float* bk   = (const float*)d_in[7];
    const float* wv   = (const float*)d_in[8];
    const float* bv   = (const float*)d_in[9];
    const float* wo   = (const float*)d_in[10];
    const float* bo   = (const float*)d_in[11];
    float* out = (float*)d_out;

    split_x3<<<dim3(M_ * D_ / 4 / 256, 3), 256>>>(q, k, v);
    split_w4<<<dim3(D_ * D_ / 4 / 256, 4), 256>>>(wq, wk, wv, wo);

    gemm_mma<1><<<dim3(D_ / 128, M_ / 128, 3), 256>>>(bq, bk, bv, nullptr);

    flash_mma<<<dim3(S_ / 128, H_, B_), 256>>>(mask);

    gemm_mma<0><<<dim3(D_ / 128, M_ / 128), 256>>>(bo, bo, bo, out);
}

// round 11
// speedup vs baseline: 1.5348x; 1.5348x over previous
#include <cuda_runtime.h>
#include <cuda_bf16.h>
#include <cstdint>
#include <cstddef>

#define B_  8
#define S_  1024
#define D_  1024
#define H_  16
#define DK_ 64
#define M_  (B_*S_)   // 8192
#define MD_ ((size_t)M_*D_)
#define DD_ ((size_t)D_*D_)

// ---------------------------------------------------------------------------
// Scratch (__device__ globals; allocation-free rule)
// ---------------------------------------------------------------------------
__device__ __nv_bfloat16 g_Xhi[3*MD_];  // split inputs q,k,v
__device__ __nv_bfloat16 g_Xlo[3*MD_];
__device__ __nv_bfloat16 g_Whi[4*DD_];  // split weights wq,wk,wv,wo
__device__ __nv_bfloat16 g_Wlo[4*DD_];
__device__ __nv_bfloat16 g_Ohi[MD_];    // split attention output [M,D]
__device__ __nv_bfloat16 g_Olo[MD_];

// head-major [B,H,S,DK] split Q/K/V
__device__ __nv_bfloat16 g_Qhi[MD_];
__device__ __nv_bfloat16 g_Qlo[MD_];
__device__ __nv_bfloat16 g_Khi[MD_];
__device__ __nv_bfloat16 g_Klo[MD_];
__device__ __nv_bfloat16 g_Vhi[MD_];
__device__ __nv_bfloat16 g_Vlo[MD_];

// ---------------------------------------------------------------------------
// PTX helpers — base ISA only: ldmatrix, mma.sync, cp.async
// ---------------------------------------------------------------------------
__device__ __forceinline__ uint32_t s2u(const void* p) {
    uint32_t a;
    asm("{ .reg .u64 t; cvta.to.shared.u64 t, %1; cvt.u32.u64 %0, t; }"
        : "=r"(a) : "l"(p));
    return a;
}

#define LDSM_X4(r0, r1, r2, r3, addr) \
    asm volatile("ldmatrix.sync.aligned.m8n8.x4.shared.b16 {%0,%1,%2,%3}, [%4];" \
        : "=r"(r0), "=r"(r1), "=r"(r2), "=r"(r3) : "r"(addr))

#define LDSM_X4T(r0, r1, r2, r3, addr) \
    asm volatile("ldmatrix.sync.aligned.m8n8.x4.trans.shared.b16 {%0,%1,%2,%3}, [%4];" \
        : "=r"(r0), "=r"(r1), "=r"(r2), "=r"(r3) : "r"(addr))

#define MMA16816(d, a, b0, b1) \
    asm volatile("mma.sync.aligned.m16n8k16.row.col.f32.bf16.bf16.f32 " \
        "{%0,%1,%2,%3}, {%4,%5,%6,%7}, {%8,%9}, {%0,%1,%2,%3};" \
        : "+f"((d)[0]), "+f"((d)[1]), "+f"((d)[2]), "+f"((d)[3]) \
        : "r"((a)[0]), "r"((a)[1]), "r"((a)[2]), "r"((a)[3]), "r"(b0), "r"(b1))

__device__ __forceinline__ void cpasync16(uint32_t dst, const void* src) {
    asm volatile("cp.async.cg.shared.global [%0], [%1], 16;" :: "r"(dst), "l"(src));
}
#define CP_COMMIT()  asm volatile("cp.async.commit_group;" ::: "memory")
#define CP_WAIT1()   asm volatile("cp.async.wait_group 1;" ::: "memory")
#define CP_WAIT0()   asm volatile("cp.async.wait_group 0;" ::: "memory")

// fp32 pair -> packed bf16x2 hi + lo (residual)
__device__ __forceinline__ void split2(float x, float y, uint32_t& hi, uint32_t& lo) {
    __nv_bfloat16 hx = __float2bfloat16(x), hy = __float2bfloat16(y);
    __nv_bfloat162 h2(hx, hy);
    hi = *reinterpret_cast<uint32_t*>(&h2);
    __nv_bfloat162 l2(__float2bfloat16(x - __bfloat162float(hx)),
                      __float2bfloat16(y - __bfloat162float(hy)));
    lo = *reinterpret_cast<uint32_t*>(&l2);
}

// ---------------------------------------------------------------------------
// Split converters (fp32 -> hi/lo bf16), batched over inputs / weights.
// ---------------------------------------------------------------------------
__global__ __launch_bounds__(256) void split_x3(
    const float* __restrict__ q, const float* __restrict__ k,
    const float* __restrict__ v)
{
    const int z = blockIdx.y;
    const float* __restrict__ s = (z == 0) ? q : (z == 1) ? k : v;
    const size_t base = (size_t)z * MD_;
    const int i = blockIdx.x * 256 + threadIdx.x;         // < M*D/4
    float4 vv = ((const float4*)s)[i];
    uint32_t h0, l0, h1, l1;
    split2(vv.x, vv.y, h0, l0);
    split2(vv.z, vv.w, h1, l1);
    uint32_t* hp = (uint32_t*)(g_Xhi + base);
    uint32_t* lp = (uint32_t*)(g_Xlo + base);
    hp[2 * i] = h0; hp[2 * i + 1] = h1;
    lp[2 * i] = l0; lp[2 * i + 1] = l1;
}

__global__ __launch_bounds__(256) void split_w4(
    const float* __restrict__ wq, const float* __restrict__ wk,
    const float* __restrict__ wv, const float* __restrict__ wo)
{
    const int z = blockIdx.y;
    const float* __restrict__ s = (z == 0) ? wq : (z == 1) ? wk : (z == 2) ? wv : wo;
    const size_t base = (size_t)z * DD_;
    const int i = blockIdx.x * 256 + threadIdx.x;         // < D*D/4
    float4 vv = ((const float4*)s)[i];
    uint32_t h0, l0, h1, l1;
    split2(vv.x, vv.y, h0, l0);
    split2(vv.z, vv.w, h1, l1);
    uint32_t* hp = (uint32_t*)(g_Whi + base);
    uint32_t* lp = (uint32_t*)(g_Wlo + base);
    hp[2 * i] = h0; hp[2 * i + 1] = h1;
    lp[2 * i] = l0; lp[2 * i + 1] = l1;
}

// ---------------------------------------------------------------------------
// HMMA split-bf16 GEMM: C[m,n] = sum_k X[m,k]*W[n,k] + bias[n]
// Block 128x128, 8 warps (4m x 2n), k-chunk 16, 3-stage cp.async, 48 KB smem.
// __launch_bounds__(256, 2): 2 CTAs/SM.
// MODE 1: batched QKV (blockIdx.z selects input/weight/bias/dest, split write).
// MODE 0: output GEMM (X = g_Ohi/Olo, W slot 3, fp32 write to Y).
// ---------------------------------------------------------------------------
#define MAT_BYTES 4096       // 128 rows * 32 B
#define NCHUNK    (D_ / 16)  // 64

template <int MODE>
__global__ __launch_bounds__(256, 2) void gemm_mma(
    const float* __restrict__ b0p, const float* __restrict__ b1p,
    const float* __restrict__ b2p, float* __restrict__ Y)
{
    __shared__ __nv_bfloat16 smem[3 * 4 * 128 * 16];   // 48 KB
    const uint32_t sb = s2u(smem);

    const int z = (MODE == 1) ? blockIdx.z : 3;
    const __nv_bfloat16* __restrict__ Xhi = (MODE == 1) ? g_Xhi + (size_t)z * MD_ : g_Ohi;
    const __nv_bfloat16* __restrict__ Xlo = (MODE == 1) ? g_Xlo + (size_t)z * MD_ : g_Olo;
    const __nv_bfloat16* __restrict__ Whi = g_Whi + (size_t)z * DD_;
    const __nv_bfloat16* __restrict__ Wlo = g_Wlo + (size_t)z * DD_;
    const float* __restrict__ bias =
        (MODE == 1) ? ((z == 0) ? b0p : (z == 1) ? b1p : b2p) : b0p;

    const int tid  = threadIdx.x;
    const int wid  = tid >> 5, lane = tid & 31;
    const int wm0  = (wid & 3) * 32;
    const int wn0  = (wid >> 2) * 64;
    const int m0   = blockIdx.y * 128, n0 = blockIdx.x * 128;

    auto sm_off = [](int row, int ck) -> uint32_t {
        return (uint32_t)(row * 32 + ((ck ^ ((row >> 2) & 1)) << 4));
    };

    auto load_stage = [&](int c, int stage) {
        const int k0 = c * 16;
#pragma unroll
        for (int i = 0; i < 4; ++i) {
            const int qq  = tid + i * 256;
            const int mat = qq >> 8, idx = qq & 255;
            const int row = idx >> 1, ck = idx & 1;
            uint32_t dst = sb + (uint32_t)(stage * 4 + mat) * MAT_BYTES + sm_off(row, ck);
            const __nv_bfloat16* g =
                (mat == 0) ? Xhi : (mat == 1) ? Xlo : (mat == 2) ? Whi : Wlo;
            const int grow = (mat < 2) ? (m0 + row) : (n0 + row);
            cpasync16(dst, g + (size_t)grow * D_ + k0 + ck * 8);
        }
        CP_COMMIT();
    };

    float acc[2][8][4];
#pragma unroll
    for (int mt = 0; mt < 2; ++mt)
#pragma unroll
        for (int nt = 0; nt < 8; ++nt)
#pragma unroll
            for (int r = 0; r < 4; ++r) acc[mt][nt][r] = 0.f;

    load_stage(0, 0);
    load_stage(1, 1);

    for (int c = 0; c < NCHUNK; ++c) {
        if (c == NCHUNK - 1) { CP_WAIT0(); } else { CP_WAIT1(); }
        __syncthreads();
        if (c + 2 < NCHUNK) load_stage(c + 2, (c + 2) % 3);

        const int stage = c % 3;
        const uint32_t ahB = sb + (uint32_t)(stage * 4 + 0) * MAT_BYTES;
        const uint32_t alB = sb + (uint32_t)(stage * 4 + 1) * MAT_BYTES;
        const uint32_t bhB = sb + (uint32_t)(stage * 4 + 2) * MAT_BYTES;
        const uint32_t blB = sb + (uint32_t)(stage * 4 + 3) * MAT_BYTES;

        const int lrow = lane & 15, lck = lane >> 4;

        uint32_t ah[2][4], al[2][4], bb[4][4];
#pragma unroll
        for (int mt = 0; mt < 2; ++mt) {
            LDSM_X4(ah[mt][0], ah[mt][1], ah[mt][2], ah[mt][3],
                    ahB + sm_off(wm0 + mt * 16 + lrow, lck));
            LDSM_X4(al[mt][0], al[mt][1], al[mt][2], al[mt][3],
                    alB + sm_off(wm0 + mt * 16 + lrow, lck));
        }
#pragma unroll
        for (int bt = 0; bt < 4; ++bt)
            LDSM_X4(bb[bt][0], bb[bt][1], bb[bt][2], bb[bt][3],
                    bhB + sm_off(wn0 + bt * 16 + lrow, lck));

#pragma unroll
        for (int mt = 0; mt < 2; ++mt)
#pragma unroll
            for (int bt = 0; bt < 4; ++bt) {
                MMA16816(acc[mt][bt * 2 + 0], ah[mt], bb[bt][0], bb[bt][2]);
                MMA16816(acc[mt][bt * 2 + 1], ah[mt], bb[bt][1], bb[bt][3]);
                MMA16816(acc[mt][bt * 2 + 0], al[mt], bb[bt][0], bb[bt][2]);
                MMA16816(acc[mt][bt * 2 + 1], al[mt], bb[bt][1], bb[bt][3]);
            }

#pragma unroll
        for (int bt = 0; bt < 4; ++bt)
            LDSM_X4(bb[bt][0], bb[bt][1], bb[bt][2], bb[bt][3],
                    blB + sm_off(wn0 + bt * 16 + lrow, lck));
#pragma unroll
        for (int mt = 0; mt < 2; ++mt)
#pragma unroll
            for (int bt = 0; bt < 4; ++bt) {
                MMA16816(acc[mt][bt * 2 + 0], ah[mt], bb[bt][0], bb[bt][2]);
                MMA16816(acc[mt][bt * 2 + 1], ah[mt], bb[bt][1], bb[bt][3]);
            }

        __syncthreads();
    }

    const int trow = lane >> 2, tcol = (lane & 3) * 2;
#pragma unroll
    for (int mt = 0; mt < 2; ++mt) {
#pragma unroll
        for (int nt = 0; nt < 8; ++nt) {
            const int col = n0 + wn0 + (nt >> 1) * 16 + (nt & 1) * 8 + tcol;
            const float2 bv = *(const float2*)&bias[col];
#pragma unroll
            for (int rh = 0; rh < 2; ++rh) {
                const int row = m0 + wm0 + mt * 16 + trow + rh * 8;
                float2 o = make_float2(acc[mt][nt][rh * 2 + 0] + bv.x,
                                       acc[mt][nt][rh * 2 + 1] + bv.y);
                if (MODE == 0) {
                    *(float2*)&Y[(size_t)row * D_ + col] = o;
                } else {
                    const int b = row >> 10, s = row & 1023;
                    const int h = col >> 6, dk = col & 63;
                    const size_t idx = (((size_t)(b * H_ + h) * S_ + s) << 6) + dk;
                    uint32_t hi, lo;
                    split2(o.x, o.y, hi, lo);
                    __nv_bfloat16* dh = (z == 0) ? g_Qhi : (z == 1) ? g_Khi : g_Vhi;
                    __nv_bfloat16* dl = (z == 0) ? g_Qlo : (z == 1) ? g_Klo : g_Vlo;
                    *(uint32_t*)&dh[idx] = hi;
                    *(uint32_t*)&dl[idx] = lo;
                }
            }
        }
    }
}

// ---------------------------------------------------------------------------
// Flash attention via split-bf16 mma.sync.
// Block = (128 q-rows, h, b); 8 warps x 16 q-rows; k-tile = 64 keys.
// Q stays RESIDENT in smem (32 KB region); Q fragments re-loaded per k-chunk
// via LDSM instead of being held in 32 registers -> fits the 128-reg cap of
// __launch_bounds__(256, 2) WITHOUT spilling. smem/CTA = 64 KB (2 CTAs/SM).
// K and V staged in separate cp.async groups: V load hidden behind S/softmax.
// ---------------------------------------------------------------------------
#define SMOFF(r, c) ((uint32_t)((r) * 128 + ((((c) ^ ((r) & 7))) << 4)))
#define SCL2E 0.1803368801111204f   // 0.125 * log2(e)
// smem layout (bf16 counts): Qhi@0, Qlo@8192, Khi@16384, Klo@20480,
//                            Vhi@24576, Vlo@28672  (x2 bytes)
#define FQH 0u
#define FQL 16384u
#define FKH 32768u
#define FKL 40960u
#define FVH 49152u
#define FVL 57344u

__global__ __launch_bounds__(256, 2) void flash_mma(const int* __restrict__ mask)
{
    __shared__ __nv_bfloat16 smem[32768];   // 64 KB
    const uint32_t sb = s2u(smem);

    const int tid = threadIdx.x, wid = tid >> 5, lane = tid & 31;
    const int h = blockIdx.y, b = blockIdx.z;
    const int q0 = blockIdx.x * 128;
    const size_t bh = (size_t)(b * H_ + h) * S_;

    // ---- prologue: stage Q hi/lo (resident for the whole kernel) ----
#pragma unroll
    for (int i = 0; i < 8; ++i) {
        int t = tid + i * 256;                       // 0..2047
        int mat = t >> 10, r = (t >> 3) & 127, ck = t & 7;
        const __nv_bfloat16* g = mat ? g_Qlo : g_Qhi;
        cpasync16(sb + (uint32_t)mat * 16384u + SMOFF(r, ck),
                  g + ((bh + q0 + r) << 6) + ck * 8);
    }
    CP_COMMIT();

    const int lr = lane & 15, lc = lane >> 4;

    float of[8][4];
    float mrow[2] = {-1e30f, -1e30f}, lrow[2] = {0.f, 0.f};
#pragma unroll
    for (int j = 0; j < 8; ++j)
#pragma unroll
        for (int r = 0; r < 4; ++r) of[j][r] = 0.f;

    const int trow = lane >> 2, tcol2 = (lane & 3) * 2;
    const int qrow0 = q0 + wid * 16 + trow;
    const int* mrow0 = mask + ((size_t)b * S_ + qrow0) * S_;
    const int* mrow1 = mrow0 + 8 * S_;

    for (int kt = 0; kt < 16; ++kt) {
        __syncthreads();                       // prior tile fully consumed
        const int k0g = kt * 64;
        // K group (Khi, Klo)
#pragma unroll
        for (int i = 0; i < 4; ++i) {
            int t = tid + i * 256;             // 0..1023
            int mat = t >> 9, r = (t >> 3) & 63, ck = t & 7;
            const __nv_bfloat16* g = (mat == 0) ? g_Khi : g_Klo;
            cpasync16(sb + FKH + (uint32_t)mat * 8192u + SMOFF(r, ck),
                      g + ((bh + k0g + r) << 6) + ck * 8);
        }
        CP_COMMIT();
        // V group (Vhi, Vlo)
#pragma unroll
        for (int i = 4; i < 8; ++i) {
            int t = tid + i * 256;             // 1024..2047
            int mat = t >> 9, r = (t >> 3) & 63, ck = t & 7;   // mat = 2,3
            const __nv_bfloat16* g = (mat == 2) ? g_Vhi : g_Vlo;
            cpasync16(sb + FKH + (uint32_t)mat * 8192u + SMOFF(r, ck),
                      g + ((bh + k0g + r) << 6) + ck * 8);
        }
        CP_COMMIT();

        CP_WAIT1();                            // K (and Q on kt=0) ready
        __syncthreads();

        // ---- S = Q K^T (hh + hl + lh); Q frags re-loaded from smem ----
        float sf[8][4];
#pragma unroll
        for (int j = 0; j < 8; ++j)
#pragma unroll
            for (int r = 0; r < 4; ++r) sf[j][r] = 0.f;

#pragma unroll
        for (int t = 0; t < 4; ++t) {
            uint32_t qh[4], ql[4];
            LDSM_X4(qh[0], qh[1], qh[2], qh[3],
                    sb + FQH + SMOFF(wid * 16 + lr, 2 * t + lc));
            LDSM_X4(ql[0], ql[1], ql[2], ql[3],
                    sb + FQL + SMOFF(wid * 16 + lr, 2 * t + lc));
#pragma unroll
            for (int nb = 0; nb < 4; ++nb) {
                uint32_t k0r, k1r, k2r, k3r, l0r, l1r, l2r, l3r;
                LDSM_X4(k0r, k1r, k2r, k3r,
                        sb + FKH + SMOFF(nb * 16 + lr, 2 * t + lc));
                LDSM_X4(l0r, l1r, l2r, l3r,
                        sb + FKL + SMOFF(nb * 16 + lr, 2 * t + lc));
                MMA16816(sf[2 * nb + 0], qh, k0r, k2r);
                MMA16816(sf[2 * nb + 1], qh, k1r, k3r);
                MMA16816(sf[2 * nb + 0], qh, l0r, l2r);
                MMA16816(sf[2 * nb + 1], qh, l1r, l3r);
                MMA16816(sf[2 * nb + 0], ql, k0r, k2r);
                MMA16816(sf[2 * nb + 1], ql, k1r, k3r);
            }
        }

        // ---- scale (exp2 domain) + mask ----
#pragma unroll
        for (int j = 0; j < 8; ++j) {
            const int col = k0g + j * 8 + tcol2;
            int2 m0v = *(const int2*)&mrow0[col];
            int2 m1v = *(const int2*)&mrow1[col];
            sf[j][0] = m0v.x ? sf[j][0] * SCL2E : -1e30f;
            sf[j][1] = m0v.y ? sf[j][1] * SCL2E : -1e30f;
            sf[j][2] = m1v.x ? sf[j][2] * SCL2E : -1e30f;
            sf[j][3] = m1v.y ? sf[j][3] * SCL2E : -1e30f;
        }

        // ---- online softmax (exp2 domain; quad = lanes l^1, l^2) ----
#pragma unroll
        for (int hh = 0; hh < 2; ++hh) {
            float rm = -1e30f;
#pragma unroll
            for (int j = 0; j < 8; ++j)
                rm = fmaxf(rm, fmaxf(sf[j][2 * hh], sf[j][2 * hh + 1]));
            rm = fmaxf(rm, __shfl_xor_sync(0xffffffffu, rm, 1));
            rm = fmaxf(rm, __shfl_xor_sync(0xffffffffu, rm, 2));
            float mnew  = fmaxf(mrow[hh], rm);
            float alpha = exp2f(mrow[hh] - mnew);
            mrow[hh] = mnew;
            float ps = 0.f;
#pragma unroll
            for (int j = 0; j < 8; ++j) {
                sf[j][2 * hh]     = exp2f(sf[j][2 * hh] - mnew);
                sf[j][2 * hh + 1] = exp2f(sf[j][2 * hh + 1] - mnew);
                ps += sf[j][2 * hh] + sf[j][2 * hh + 1];
            }
            ps += __shfl_xor_sync(0xffffffffu, ps, 1);
            ps += __shfl_xor_sync(0xffffffffu, ps, 2);
            lrow[hh] = lrow[hh] * alpha + ps;
#pragma unroll
            for (int j = 0; j < 8; ++j) {
                of[j][2 * hh]     *= alpha;
                of[j][2 * hh + 1] *= alpha;
            }
        }

        CP_WAIT0();                            // V ready
        __syncthreads();

        // ---- O += P V (P split in registers; V via ldmatrix.trans) ----
#pragma unroll
        for (int t = 0; t < 4; ++t) {
            uint32_t pah[4], pal[4];
            split2(sf[2 * t][0],     sf[2 * t][1],     pah[0], pal[0]);
            split2(sf[2 * t][2],     sf[2 * t][3],     pah[1], pal[1]);
            split2(sf[2 * t + 1][0], sf[2 * t + 1][1], pah[2], pal[2]);
            split2(sf[2 * t + 1][2], sf[2 * t + 1][3], pah[3], pal[3]);
#pragma unroll
            for (int nb = 0; nb < 4; ++nb) {
                uint32_t v0, v1, v2, v3, w0, w1, w2, w3;
                LDSM_X4T(v0, v1, v2, v3, sb + FVH + SMOFF(t * 16 + lr, 2 * nb + lc));
                LDSM_X4T(w0, w1, w2, w3, sb + FVL + SMOFF(t * 16 + lr, 2 * nb + lc));
                MMA16816(of[2 * nb + 0], pah, v0, v1);
                MMA16816(of[2 * nb + 1], pah, v2, v3);
                MMA16816(of[2 * nb + 0], pah, w0, w1);
                MMA16816(of[2 * nb + 1], pah, w2, w3);
                MMA16816(of[2 * nb + 0], pal, v0, v1);
                MMA16816(of[2 * nb + 1], pal, v2, v3);
            }
        }
    }

    // ---- epilogue: normalize, split, write hi/lo bf16 [M,D] ----
#pragma unroll
    for (int hh = 0; hh < 2; ++hh) {
        const float inv = (lrow[hh] > 0.f) ? (1.f / lrow[hh]) : 0.f;
        const int row = qrow0 + 8 * hh;
        const size_t rb = ((size_t)b * S_ + row) * D_ + h * 64;
#pragma unroll
        for (int j = 0; j < 8; ++j) {
            uint32_t hi, lo;
            split2(of[j][2 * hh] * inv, of[j][2 * hh + 1] * inv, hi, lo);
            *(uint32_t*)&g_Ohi[rb + j * 8 + tcol2] = hi;
            *(uint32_t*)&g_Olo[rb + j * 8 + tcol2] = lo;
        }
    }
}

// ---------------------------------------------------------------------------
// kernel_launch: pure kernel launches, nothing else.
// ---------------------------------------------------------------------------
extern "C" void kernel_launch(void* const* d_in, const int* in_sizes, int n_in,
                              void* d_out, int out_size)
{
    const float* q    = (const float*)d_in[0];
    const float* k    = (const float*)d_in[1];
    const float* v    = (const float*)d_in[2];
    const int*   mask = (const int*)d_in[3];
    const float* wq   = (const float*)d_in[4];
    const float* bq   = (const float*)d_in[5];
    const float* wk   = (const float*)d_in[6];
    const float* bk   = (const float*)d_in[7];
    const float* wv   = (const float*)d_in[8];
    const float* bv   = (const float*)d_in[9];
    const float* wo   = (const float*)d_in[10];
    const float* bo   = (const float*)d_in[11];
    float* out = (float*)d_out;

    split_x3<<<dim3(M_ * D_ / 4 / 256, 3), 256>>>(q, k, v);
    split_w4<<<dim3(D_ * D_ / 4 / 256, 4), 256>>>(wq, wk, wv, wo);

    gemm_mma<1><<<dim3(D_ / 128, M_ / 128, 3), 256>>>(bq, bk, bv, nullptr);

    flash_mma<<<dim3(S_ / 128, H_, B_), 256>>>(mask);

    gemm_mma<0><<<dim3(D_ / 128, M_ / 128), 256>>>(bo, bo, bo, out);
}

// round 12
// speedup vs baseline: 1.5412x; 1.0041x over previous
#include <cuda_runtime.h>
#include <cuda_bf16.h>
#include <cstdint>
#include <cstddef>

#define B_  8
#define S_  1024
#define D_  1024
#define H_  16
#define DK_ 64
#define M_  (B_*S_)   // 8192
#define MD_ ((size_t)M_*D_)
#define DD_ ((size_t)D_*D_)

// ---------------------------------------------------------------------------
// Scratch (__device__ globals; allocation-free rule)
// ---------------------------------------------------------------------------
__device__ __nv_bfloat16 g_Xhi[3*MD_];  // split inputs q,k,v
__device__ __nv_bfloat16 g_Xlo[3*MD_];
__device__ __nv_bfloat16 g_Whi[4*DD_];  // split weights wq,wk,wv,wo
__device__ __nv_bfloat16 g_Wlo[4*DD_];
__device__ __nv_bfloat16 g_Ohi[MD_];    // split attention output [M,D]
__device__ __nv_bfloat16 g_Olo[MD_];

// head-major [B,H,S,DK] split Q/K/V
__device__ __nv_bfloat16 g_Qhi[MD_];
__device__ __nv_bfloat16 g_Qlo[MD_];
__device__ __nv_bfloat16 g_Khi[MD_];
__device__ __nv_bfloat16 g_Klo[MD_];
__device__ __nv_bfloat16 g_Vhi[MD_];
__device__ __nv_bfloat16 g_Vlo[MD_];

// ---------------------------------------------------------------------------
// PTX helpers — base ISA only: ldmatrix, mma.sync, cp.async
// ---------------------------------------------------------------------------
__device__ __forceinline__ uint32_t s2u(const void* p) {
    uint32_t a;
    asm("{ .reg .u64 t; cvta.to.shared.u64 t, %1; cvt.u32.u64 %0, t; }"
        : "=r"(a) : "l"(p));
    return a;
}

#define LDSM_X4(r0, r1, r2, r3, addr) \
    asm volatile("ldmatrix.sync.aligned.m8n8.x4.shared.b16 {%0,%1,%2,%3}, [%4];" \
        : "=r"(r0), "=r"(r1), "=r"(r2), "=r"(r3) : "r"(addr))

#define LDSM_X4T(r0, r1, r2, r3, addr) \
    asm volatile("ldmatrix.sync.aligned.m8n8.x4.trans.shared.b16 {%0,%1,%2,%3}, [%4];" \
        : "=r"(r0), "=r"(r1), "=r"(r2), "=r"(r3) : "r"(addr))

#define MMA16816(d, a, b0, b1) \
    asm volatile("mma.sync.aligned.m16n8k16.row.col.f32.bf16.bf16.f32 " \
        "{%0,%1,%2,%3}, {%4,%5,%6,%7}, {%8,%9}, {%0,%1,%2,%3};" \
        : "+f"((d)[0]), "+f"((d)[1]), "+f"((d)[2]), "+f"((d)[3]) \
        : "r"((a)[0]), "r"((a)[1]), "r"((a)[2]), "r"((a)[3]), "r"(b0), "r"(b1))

__device__ __forceinline__ void cpasync16(uint32_t dst, const void* src) {
    asm volatile("cp.async.cg.shared.global [%0], [%1], 16;" :: "r"(dst), "l"(src));
}
#define CP_COMMIT()  asm volatile("cp.async.commit_group;" ::: "memory")
#define CP_WAIT1()   asm volatile("cp.async.wait_group 1;" ::: "memory")
#define CP_WAIT0()   asm volatile("cp.async.wait_group 0;" ::: "memory")

// fp32 pair -> packed bf16x2 hi + lo (residual)
__device__ __forceinline__ void split2(float x, float y, uint32_t& hi, uint32_t& lo) {
    __nv_bfloat16 hx = __float2bfloat16(x), hy = __float2bfloat16(y);
    __nv_bfloat162 h2(hx, hy);
    hi = *reinterpret_cast<uint32_t*>(&h2);
    __nv_bfloat162 l2(__float2bfloat16(x - __bfloat162float(hx)),
                      __float2bfloat16(y - __bfloat162float(hy)));
    lo = *reinterpret_cast<uint32_t*>(&l2);
}

// ---------------------------------------------------------------------------
// Split converters (fp32 -> hi/lo bf16), batched over inputs / weights.
// ---------------------------------------------------------------------------
__global__ __launch_bounds__(256) void split_x3(
    const float* __restrict__ q, const float* __restrict__ k,
    const float* __restrict__ v)
{
    const int z = blockIdx.y;
    const float* __restrict__ s = (z == 0) ? q : (z == 1) ? k : v;
    const size_t base = (size_t)z * MD_;
    const int i = blockIdx.x * 256 + threadIdx.x;         // < M*D/4
    float4 vv = ((const float4*)s)[i];
    uint32_t h0, l0, h1, l1;
    split2(vv.x, vv.y, h0, l0);
    split2(vv.z, vv.w, h1, l1);
    uint32_t* hp = (uint32_t*)(g_Xhi + base);
    uint32_t* lp = (uint32_t*)(g_Xlo + base);
    hp[2 * i] = h0; hp[2 * i + 1] = h1;
    lp[2 * i] = l0; lp[2 * i + 1] = l1;
}

__global__ __launch_bounds__(256) void split_w4(
    const float* __restrict__ wq, const float* __restrict__ wk,
    const float* __restrict__ wv, const float* __restrict__ wo)
{
    const int z = blockIdx.y;
    const float* __restrict__ s = (z == 0) ? wq : (z == 1) ? wk : (z == 2) ? wv : wo;
    const size_t base = (size_t)z * DD_;
    const int i = blockIdx.x * 256 + threadIdx.x;         // < D*D/4
    float4 vv = ((const float4*)s)[i];
    uint32_t h0, l0, h1, l1;
    split2(vv.x, vv.y, h0, l0);
    split2(vv.z, vv.w, h1, l1);
    uint32_t* hp = (uint32_t*)(g_Whi + base);
    uint32_t* lp = (uint32_t*)(g_Wlo + base);
    hp[2 * i] = h0; hp[2 * i + 1] = h1;
    lp[2 * i] = l0; lp[2 * i + 1] = l1;
}

// ---------------------------------------------------------------------------
// HMMA split-bf16 GEMM: C[m,n] = sum_k X[m,k]*W[n,k] + bias[n]
// Block 128x128, 8 warps (4m x 2n), k-chunk 16, 3-stage cp.async, 48 KB smem.
// __launch_bounds__(256, 2): 2 CTAs/SM.
// MODE 1: batched QKV (blockIdx.z selects input/weight/bias/dest, split write).
// MODE 0: output GEMM (X = g_Ohi/Olo, W slot 3, fp32 write to Y).
// ---------------------------------------------------------------------------
#define MAT_BYTES 4096       // 128 rows * 32 B
#define NCHUNK    (D_ / 16)  // 64

template <int MODE>
__global__ __launch_bounds__(256, 2) void gemm_mma(
    const float* __restrict__ b0p, const float* __restrict__ b1p,
    const float* __restrict__ b2p, float* __restrict__ Y)
{
    __shared__ __nv_bfloat16 smem[3 * 4 * 128 * 16];   // 48 KB
    const uint32_t sb = s2u(smem);

    const int z = (MODE == 1) ? blockIdx.z : 3;
    const __nv_bfloat16* __restrict__ Xhi = (MODE == 1) ? g_Xhi + (size_t)z * MD_ : g_Ohi;
    const __nv_bfloat16* __restrict__ Xlo = (MODE == 1) ? g_Xlo + (size_t)z * MD_ : g_Olo;
    const __nv_bfloat16* __restrict__ Whi = g_Whi + (size_t)z * DD_;
    const __nv_bfloat16* __restrict__ Wlo = g_Wlo + (size_t)z * DD_;
    const float* __restrict__ bias =
        (MODE == 1) ? ((z == 0) ? b0p : (z == 1) ? b1p : b2p) : b0p;

    const int tid  = threadIdx.x;
    const int wid  = tid >> 5, lane = tid & 31;
    const int wm0  = (wid & 3) * 32;
    const int wn0  = (wid >> 2) * 64;
    const int m0   = blockIdx.y * 128, n0 = blockIdx.x * 128;

    auto sm_off = [](int row, int ck) -> uint32_t {
        return (uint32_t)(row * 32 + ((ck ^ ((row >> 2) & 1)) << 4));
    };

    auto load_stage = [&](int c, int stage) {
        const int k0 = c * 16;
#pragma unroll
        for (int i = 0; i < 4; ++i) {
            const int qq  = tid + i * 256;
            const int mat = qq >> 8, idx = qq & 255;
            const int row = idx >> 1, ck = idx & 1;
            uint32_t dst = sb + (uint32_t)(stage * 4 + mat) * MAT_BYTES + sm_off(row, ck);
            const __nv_bfloat16* g =
                (mat == 0) ? Xhi : (mat == 1) ? Xlo : (mat == 2) ? Whi : Wlo;
            const int grow = (mat < 2) ? (m0 + row) : (n0 + row);
            cpasync16(dst, g + (size_t)grow * D_ + k0 + ck * 8);
        }
        CP_COMMIT();
    };

    float acc[2][8][4];
#pragma unroll
    for (int mt = 0; mt < 2; ++mt)
#pragma unroll
        for (int nt = 0; nt < 8; ++nt)
#pragma unroll
            for (int r = 0; r < 4; ++r) acc[mt][nt][r] = 0.f;

    load_stage(0, 0);
    load_stage(1, 1);

    for (int c = 0; c < NCHUNK; ++c) {
        if (c == NCHUNK - 1) { CP_WAIT0(); } else { CP_WAIT1(); }
        __syncthreads();
        if (c + 2 < NCHUNK) load_stage(c + 2, (c + 2) % 3);

        const int stage = c % 3;
        const uint32_t ahB = sb + (uint32_t)(stage * 4 + 0) * MAT_BYTES;
        const uint32_t alB = sb + (uint32_t)(stage * 4 + 1) * MAT_BYTES;
        const uint32_t bhB = sb + (uint32_t)(stage * 4 + 2) * MAT_BYTES;
        const uint32_t blB = sb + (uint32_t)(stage * 4 + 3) * MAT_BYTES;

        const int lrow = lane & 15, lck = lane >> 4;

        uint32_t ah[2][4], al[2][4], bb[4][4];
#pragma unroll
        for (int mt = 0; mt < 2; ++mt) {
            LDSM_X4(ah[mt][0], ah[mt][1], ah[mt][2], ah[mt][3],
                    ahB + sm_off(wm0 + mt * 16 + lrow, lck));
            LDSM_X4(al[mt][0], al[mt][1], al[mt][2], al[mt][3],
                    alB + sm_off(wm0 + mt * 16 + lrow, lck));
        }
#pragma unroll
        for (int bt = 0; bt < 4; ++bt)
            LDSM_X4(bb[bt][0], bb[bt][1], bb[bt][2], bb[bt][3],
                    bhB + sm_off(wn0 + bt * 16 + lrow, lck));

#pragma unroll
        for (int mt = 0; mt < 2; ++mt)
#pragma unroll
            for (int bt = 0; bt < 4; ++bt) {
                MMA16816(acc[mt][bt * 2 + 0], ah[mt], bb[bt][0], bb[bt][2]);
                MMA16816(acc[mt][bt * 2 + 1], ah[mt], bb[bt][1], bb[bt][3]);
                MMA16816(acc[mt][bt * 2 + 0], al[mt], bb[bt][0], bb[bt][2]);
                MMA16816(acc[mt][bt * 2 + 1], al[mt], bb[bt][1], bb[bt][3]);
            }

#pragma unroll
        for (int bt = 0; bt < 4; ++bt)
            LDSM_X4(bb[bt][0], bb[bt][1], bb[bt][2], bb[bt][3],
                    blB + sm_off(wn0 + bt * 16 + lrow, lck));
#pragma unroll
        for (int mt = 0; mt < 2; ++mt)
#pragma unroll
            for (int bt = 0; bt < 4; ++bt) {
                MMA16816(acc[mt][bt * 2 + 0], ah[mt], bb[bt][0], bb[bt][2]);
                MMA16816(acc[mt][bt * 2 + 1], ah[mt], bb[bt][1], bb[bt][3]);
            }

        __syncthreads();
    }

    const int trow = lane >> 2, tcol = (lane & 3) * 2;
#pragma unroll
    for (int mt = 0; mt < 2; ++mt) {
#pragma unroll
        for (int nt = 0; nt < 8; ++nt) {
            const int col = n0 + wn0 + (nt >> 1) * 16 + (nt & 1) * 8 + tcol;
            const float2 bv = *(const float2*)&bias[col];
#pragma unroll
            for (int rh = 0; rh < 2; ++rh) {
                const int row = m0 + wm0 + mt * 16 + trow + rh * 8;
                float2 o = make_float2(acc[mt][nt][rh * 2 + 0] + bv.x,
                                       acc[mt][nt][rh * 2 + 1] + bv.y);
                if (MODE == 0) {
                    *(float2*)&Y[(size_t)row * D_ + col] = o;
                } else {
                    const int b = row >> 10, s = row & 1023;
                    const int h = col >> 6, dk = col & 63;
                    const size_t idx = (((size_t)(b * H_ + h) * S_ + s) << 6) + dk;
                    uint32_t hi, lo;
                    split2(o.x, o.y, hi, lo);
                    __nv_bfloat16* dh = (z == 0) ? g_Qhi : (z == 1) ? g_Khi : g_Vhi;
                    __nv_bfloat16* dl = (z == 0) ? g_Qlo : (z == 1) ? g_Klo : g_Vlo;
                    *(uint32_t*)&dh[idx] = hi;
                    *(uint32_t*)&dl[idx] = lo;
                }
            }
        }
    }
}

// ---------------------------------------------------------------------------
// Flash attention via split-bf16 mma.sync — cross-tile double buffered.
// Block = (128 q-rows, h, b); 8 warps x 16 q-rows; k-tile = 64 keys.
// smem 96 KB/CTA: Q resident (32 KB) + 2 K/V buffers (32 KB each).
// 2 CTAs/SM (192 KB smem/SM, regs capped at 128 -> no spill per round 11).
// Tile t+2 loads issue while tile t computes: cp.async latency fully hidden.
// ---------------------------------------------------------------------------
#define SMOFF(r, c) ((uint32_t)((r) * 128 + ((((c) ^ ((r) & 7))) << 4)))
#define SCL2E 0.1803368801111204f   // 0.125 * log2(e)
#define FQH 0u
#define FQL 16384u
#define KVB(s) (32768u + (uint32_t)(s) * 32768u)   // per-buffer: KH+0 KL+8192 VH+16384 VL+24576

__global__ __launch_bounds__(256, 2) void flash_mma(const int* __restrict__ mask)
{
    __shared__ __nv_bfloat16 smem[49152];   // 96 KB
    const uint32_t sb = s2u(smem);

    const int tid = threadIdx.x, wid = tid >> 5, lane = tid & 31;
    const int h = blockIdx.y, b = blockIdx.z;
    const int q0 = blockIdx.x * 128;
    const size_t bh = (size_t)(b * H_ + h) * S_;

    auto load_kv = [&](int kt, int s) {
        const int k0g = kt * 64;
        const uint32_t base = sb + KVB(s);
#pragma unroll
        for (int i = 0; i < 8; ++i) {
            int t = tid + i * 256;             // 0..2047
            int mat = t >> 9;                  // 0..3: Khi,Klo,Vhi,Vlo
            int r = (t >> 3) & 63, ck = t & 7;
            const __nv_bfloat16* g = (mat == 0) ? g_Khi : (mat == 1) ? g_Klo
                                   : (mat == 2) ? g_Vhi : g_Vlo;
            cpasync16(base + (uint32_t)mat * 8192u + SMOFF(r, ck),
                      g + ((bh + k0g + r) << 6) + ck * 8);
        }
        CP_COMMIT();
    };

    // ---- prologue: Q (resident) + tiles 0, 1 ----
#pragma unroll
    for (int i = 0; i < 8; ++i) {
        int t = tid + i * 256;                       // 0..2047
        int mat = t >> 10, r = (t >> 3) & 127, ck = t & 7;
        const __nv_bfloat16* g = mat ? g_Qlo : g_Qhi;
        cpasync16(sb + (uint32_t)mat * 16384u + SMOFF(r, ck),
                  g + ((bh + q0 + r) << 6) + ck * 8);
    }
    CP_COMMIT();
    load_kv(0, 0);
    load_kv(1, 1);

    const int lr = lane & 15, lc = lane >> 4;

    float of[8][4];
    float mrow[2] = {-1e30f, -1e30f}, lrow[2] = {0.f, 0.f};
#pragma unroll
    for (int j = 0; j < 8; ++j)
#pragma unroll
        for (int r = 0; r < 4; ++r) of[j][r] = 0.f;

    const int trow = lane >> 2, tcol2 = (lane & 3) * 2;
    const int qrow0 = q0 + wid * 16 + trow;
    const int* mrow0 = mask + ((size_t)b * S_ + qrow0) * S_;
    const int* mrow1 = mrow0 + 8 * S_;

    for (int kt = 0; kt < 16; ++kt) {
        CP_WAIT1();                            // Q + tile kt ready (kt+1 in flight)
        __syncthreads();

        const int k0g = kt * 64;
        const uint32_t kvb = sb + KVB(kt & 1);
        const uint32_t KH = kvb, KL = kvb + 8192u, VH = kvb + 16384u, VL = kvb + 24576u;

        // ---- S = Q K^T (hh + hl + lh); Q frags re-loaded from smem ----
        float sf[8][4];
#pragma unroll
        for (int j = 0; j < 8; ++j)
#pragma unroll
            for (int r = 0; r < 4; ++r) sf[j][r] = 0.f;

#pragma unroll
        for (int t = 0; t < 4; ++t) {
            uint32_t qh[4], ql[4];
            LDSM_X4(qh[0], qh[1], qh[2], qh[3],
                    sb + FQH + SMOFF(wid * 16 + lr, 2 * t + lc));
            LDSM_X4(ql[0], ql[1], ql[2], ql[3],
                    sb + FQL + SMOFF(wid * 16 + lr, 2 * t + lc));
#pragma unroll
            for (int nb = 0; nb < 4; ++nb) {
                uint32_t k0r, k1r, k2r, k3r, l0r, l1r, l2r, l3r;
                LDSM_X4(k0r, k1r, k2r, k3r, KH + SMOFF(nb * 16 + lr, 2 * t + lc));
                LDSM_X4(l0r, l1r, l2r, l3r, KL + SMOFF(nb * 16 + lr, 2 * t + lc));
                MMA16816(sf[2 * nb + 0], qh, k0r, k2r);
                MMA16816(sf[2 * nb + 1], qh, k1r, k3r);
                MMA16816(sf[2 * nb + 0], qh, l0r, l2r);
                MMA16816(sf[2 * nb + 1], qh, l1r, l3r);
                MMA16816(sf[2 * nb + 0], ql, k0r, k2r);
                MMA16816(sf[2 * nb + 1], ql, k1r, k3r);
            }
        }

        // ---- scale (exp2 domain) + mask ----
#pragma unroll
        for (int j = 0; j < 8; ++j) {
            const int col = k0g + j * 8 + tcol2;
            int2 m0v = *(const int2*)&mrow0[col];
            int2 m1v = *(const int2*)&mrow1[col];
            sf[j][0] = m0v.x ? sf[j][0] * SCL2E : -1e30f;
            sf[j][1] = m0v.y ? sf[j][1] * SCL2E : -1e30f;
            sf[j][2] = m1v.x ? sf[j][2] * SCL2E : -1e30f;
            sf[j][3] = m1v.y ? sf[j][3] * SCL2E : -1e30f;
        }

        // ---- online softmax (exp2 domain; quad = lanes l^1, l^2) ----
#pragma unroll
        for (int hh = 0; hh < 2; ++hh) {
            float rm = -1e30f;
#pragma unroll
            for (int j = 0; j < 8; ++j)
                rm = fmaxf(rm, fmaxf(sf[j][2 * hh], sf[j][2 * hh + 1]));
            rm = fmaxf(rm, __shfl_xor_sync(0xffffffffu, rm, 1));
            rm = fmaxf(rm, __shfl_xor_sync(0xffffffffu, rm, 2));
            float mnew  = fmaxf(mrow[hh], rm);
            float alpha = exp2f(mrow[hh] - mnew);
            mrow[hh] = mnew;
            float ps = 0.f;
#pragma unroll
            for (int j = 0; j < 8; ++j) {
                sf[j][2 * hh]     = exp2f(sf[j][2 * hh] - mnew);
                sf[j][2 * hh + 1] = exp2f(sf[j][2 * hh + 1] - mnew);
                ps += sf[j][2 * hh] + sf[j][2 * hh + 1];
            }
            ps += __shfl_xor_sync(0xffffffffu, ps, 1);
            ps += __shfl_xor_sync(0xffffffffu, ps, 2);
            lrow[hh] = lrow[hh] * alpha + ps;
#pragma unroll
            for (int j = 0; j < 8; ++j) {
                of[j][2 * hh]     *= alpha;
                of[j][2 * hh + 1] *= alpha;
            }
        }

        // ---- O += P V (P split in registers; V via ldmatrix.trans) ----
#pragma unroll
        for (int t = 0; t < 4; ++t) {
            uint32_t pah[4], pal[4];
            split2(sf[2 * t][0],     sf[2 * t][1],     pah[0], pal[0]);
            split2(sf[2 * t][2],     sf[2 * t][3],     pah[1], pal[1]);
            split2(sf[2 * t + 1][0], sf[2 * t + 1][1], pah[2], pal[2]);
            split2(sf[2 * t + 1][2], sf[2 * t + 1][3], pah[3], pal[3]);
#pragma unroll
            for (int nb = 0; nb < 4; ++nb) {
                uint32_t v0, v1, v2, v3, w0, w1, w2, w3;
                LDSM_X4T(v0, v1, v2, v3, VH + SMOFF(t * 16 + lr, 2 * nb + lc));
                LDSM_X4T(w0, w1, w2, w3, VL + SMOFF(t * 16 + lr, 2 * nb + lc));
                MMA16816(of[2 * nb + 0], pah, v0, v1);
                MMA16816(of[2 * nb + 1], pah, v2, v3);
                MMA16816(of[2 * nb + 0], pah, w0, w1);
                MMA16816(of[2 * nb + 1], pah, w2, w3);
                MMA16816(of[2 * nb + 0], pal, v0, v1);
                MMA16816(of[2 * nb + 1], pal, v2, v3);
            }
        }

        __syncthreads();                       // whole CTA done with buffer kt&1
        if (kt + 2 < 16) load_kv(kt + 2, kt & 1);
    }

    // ---- epilogue: normalize, split, write hi/lo bf16 [M,D] ----
#pragma unroll
    for (int hh = 0; hh < 2; ++hh) {
        const float inv = (lrow[hh] > 0.f) ? (1.f / lrow[hh]) : 0.f;
        const int row = qrow0 + 8 * hh;
        const size_t rb = ((size_t)b * S_ + row) * D_ + h * 64;
#pragma unroll
        for (int j = 0; j < 8; ++j) {
            uint32_t hi, lo;
            split2(of[j][2 * hh] * inv, of[j][2 * hh + 1] * inv, hi, lo);
            *(uint32_t*)&g_Ohi[rb + j * 8 + tcol2] = hi;
            *(uint32_t*)&g_Olo[rb + j * 8 + tcol2] = lo;
        }
    }
}

// ---------------------------------------------------------------------------
// kernel_launch: pure kernel launches, nothing else.
// ---------------------------------------------------------------------------
extern "C" void kernel_launch(void* const* d_in, const int* in_sizes, int n_in,
                              void* d_out, int out_size)
{
    const float* q    = (const float*)d_in[0];
    const float* k    = (const float*)d_in[1];
    const float* v    = (const float*)d_in[2];
    const int*   mask = (const int*)d_in[3];
    const float* wq   = (const float*)d_in[4];
    const float* bq   = (const float*)d_in[5];
    const float* wk   = (const float*)d_in[6];
    const float* bk   = (const float*)d_in[7];
    const float* wv   = (const float*)d_in[8];
    const float* bv   = (const float*)d_in[9];
    const float* wo   = (const float*)d_in[10];
    const float* bo   = (const float*)d_in[11];
    float* out = (float*)d_out;

    split_x3<<<dim3(M_ * D_ / 4 / 256, 3), 256>>>(q, k, v);
    split_w4<<<dim3(D_ * D_ / 4 / 256, 4), 256>>>(wq, wk, wv, wo);

    gemm_mma<1><<<dim3(D_ / 128, M_ / 128, 3), 256>>>(bq, bk, bv, nullptr);

    flash_mma<<<dim3(S_ / 128, H_, B_), 256>>>(mask);

    gemm_mma<0><<<dim3(D_ / 128, M_ / 128), 256>>>(bo, bo, bo, out);
}